// round 11
// baseline (speedup 1.0000x reference)
#include <cuda_runtime.h>
#include <cuda_fp16.h>
#include <cstdint>

// ---------------------------------------------------------------------------
// Problem dims
// ---------------------------------------------------------------------------
#define BATCH   2048
#define IN_DIM  4096   // K
#define OUT_DIM 4096   // N
#define K16     (IN_DIM / 16)    // 256 k-tiles of 16
#define M16     (BATCH / 16)     // 128 m-tiles of 16

// Scratch (static __device__ = sanctioned mechanism).
__device__ __align__(256) __half g_W_h[(size_t)IN_DIM * OUT_DIM];   // [K,N] fp16 (32MB)
// A in m16n8k16 FRAGMENT layout: per 16x16 tile, per lane, uint4 = (a0,a1,a2,a3)
__device__ __align__(256) uint4 g_A_f[(size_t)M16 * K16 * 32];      // 16MB
__device__ int g_ticket;

// ---------------------------------------------------------------------------
// Kernel 1 (fused prep): blocks [0,4096) decode W; blocks [4096,8192) pack A
// into fragment layout (8 warps/block, one 16x16 tile per warp).
// ---------------------------------------------------------------------------
#define DEC_BLOCKS 4096
#define AFR_BLOCKS 4096

__global__ __launch_bounds__(256) void prep_kernel(const int4* __restrict__ idx,
                                                   const float* __restrict__ mean,
                                                   const float* __restrict__ x) {
    const int b = blockIdx.x;
    if (b < DEC_BLOCKS) {
        __shared__ float sm[IN_DIM];
        #pragma unroll
        for (int i = threadIdx.x; i < IN_DIM; i += 256) sm[i] = mean[i];
        __syncthreads();

        const size_t base = (size_t)b * (256 * 4) + threadIdx.x;  // int4 units
        int4 v[4];
        #pragma unroll
        for (int p = 0; p < 4; p++) v[p] = idx[base + (size_t)p * 256];
        #pragma unroll
        for (int p = 0; p < 4; p++) {
            __half2 lo = __floats2half2_rn(sm[v[p].x], sm[v[p].y]);
            __half2 hi = __floats2half2_rn(sm[v[p].z], sm[v[p].w]);
            uint2 pk;
            pk.x = *reinterpret_cast<uint32_t*>(&lo);
            pk.y = *reinterpret_cast<uint32_t*>(&hi);
            reinterpret_cast<uint2*>(g_W_h)[base + (size_t)p * 256] = pk;
        }
    } else {
        if (b == DEC_BLOCKS && threadIdx.x == 0) g_ticket = 0;  // reset before GEMM
        // ---- A fragment pack: tile_id = 16x16 tile; m16 = tile>>8, k16 = tile&255
        const int lane = threadIdx.x & 31;
        const int tile = (b - DEC_BLOCKS) * 8 + (threadIdx.x >> 5);
        const int m16 = tile >> 8;       // /K16
        const int k16 = tile & (K16 - 1);
        const int row = m16 * 16 + (lane >> 2);
        const int col = k16 * 16 + 2 * (lane & 3);
        const float* xp = x + (size_t)row * IN_DIM + col;
        float2 f0 = *reinterpret_cast<const float2*>(xp);                      // (row,   c)
        float2 f1 = *reinterpret_cast<const float2*>(xp + 8 * IN_DIM);        // (row+8, c)
        float2 f2 = *reinterpret_cast<const float2*>(xp + 8);                 // (row,   c+8)
        float2 f3 = *reinterpret_cast<const float2*>(xp + 8 * IN_DIM + 8);    // (row+8, c+8)
        __half2 h0 = __floats2half2_rn(f0.x, f0.y);
        __half2 h1 = __floats2half2_rn(f1.x, f1.y);
        __half2 h2 = __floats2half2_rn(f2.x, f2.y);
        __half2 h3 = __floats2half2_rn(f3.x, f3.y);
        uint4 pk;
        pk.x = *reinterpret_cast<uint32_t*>(&h0);   // a0
        pk.y = *reinterpret_cast<uint32_t*>(&h1);   // a1
        pk.z = *reinterpret_cast<uint32_t*>(&h2);   // a2
        pk.w = *reinterpret_cast<uint32_t*>(&h3);   // a3
        g_A_f[(size_t)tile * 32 + lane] = pk;       // STG.128, coalesced
    }
}

// ---------------------------------------------------------------------------
// Kernel 2: persistent fp16 GEMM (fp32 accum) + bias.
// Block 128x128, 4 warps (2x2), warp tile 64x64, BK=32.
// B: 4-stage cp.async smem pipeline + ldmatrix.trans (crossbar load only).
// A: coalesced LDG.128 of pre-packed fragments, double-buffered one kt ahead.
// ---------------------------------------------------------------------------
#define BM 128
#define BN 128
#define BK 32
#define KT (IN_DIM / BK)        // 128
#define NTILES ((BATCH / BM) * (OUT_DIM / BN))   // 512
#define NWORKERS 296
#define STAGES 4
#define LDB_S 136               // B smem row stride (halves): 272B
#define B_STAGE_H (BK * LDB_S)  // 4352 halves (8704 B)
#define SMEM_BYTES (STAGES * B_STAGE_H * 2)   // 34816 B

__device__ __forceinline__ void cp_async16(__half* smem_dst, const __half* gmem_src) {
    uint32_t s = (uint32_t)__cvta_generic_to_shared(smem_dst);
    asm volatile("cp.async.cg.shared.global [%0], [%1], 16;\n" :: "r"(s), "l"(gmem_src));
}
__device__ __forceinline__ void cp_async_commit() {
    asm volatile("cp.async.commit_group;\n" ::);
}
template <int N>
__device__ __forceinline__ void cp_async_wait() {
    asm volatile("cp.async.wait_group %0;\n" :: "n"(N));
}
__device__ __forceinline__ void ldmatrix_x4_trans(uint32_t* r, const __half* p) {
    uint32_t a = (uint32_t)__cvta_generic_to_shared(p);
    asm volatile("ldmatrix.sync.aligned.m8n8.x4.trans.shared.b16 {%0,%1,%2,%3}, [%4];"
                 : "=r"(r[0]), "=r"(r[1]), "=r"(r[2]), "=r"(r[3]) : "r"(a));
}
__device__ __forceinline__ void mma_16816(float* d, const uint32_t* a, const uint32_t* b) {
    asm volatile(
        "mma.sync.aligned.m16n8k16.row.col.f32.f16.f16.f32 "
        "{%0,%1,%2,%3}, {%4,%5,%6,%7}, {%8,%9}, {%0,%1,%2,%3};"
        : "+f"(d[0]), "+f"(d[1]), "+f"(d[2]), "+f"(d[3])
        : "r"(a[0]), "r"(a[1]), "r"(a[2]), "r"(a[3]), "r"(b[0]), "r"(b[1]));
}

__global__ __launch_bounds__(128, 2) void gemm_fp16_kernel(
    const float* __restrict__ bias,
    float* __restrict__ out)
{
    extern __shared__ __half smem[];
    __shared__ int s_tile;

    const int tid  = threadIdx.x;
    const int lane = tid & 31;
    const int warpId = tid >> 5;
    const int wm = warpId >> 1;   // M offset wm*64
    const int wn = warpId & 1;    // N offset wn*64
    const int lrow = lane & 15;
    const int lcol = (lane >> 4) * 8;

    auto Bs = [&](int s) { return smem + s * B_STAGE_H; };

    auto load_stage_B = [&](int kt, int s, int col0) {
        const __half* Bg = g_W_h + (size_t)(kt * BK) * OUT_DIM + col0;
        __half* bs = Bs(s);
        #pragma unroll
        for (int p = 0; p < 4; p++) {
            int f = tid + p * 128;
            int r = f >> 4, c = (f & 15) * 8;
            cp_async16(&bs[r * LDB_S + c], Bg + (size_t)r * OUT_DIM + c);
        }
    };

    auto fetch_ticket = [&]() -> int {
        __syncthreads();
        if (tid == 0) s_tile = atomicAdd(&g_ticket, 1);
        __syncthreads();
        return s_tile;
    };

    int t = fetch_ticket();
    if (t >= NTILES) return;
    int row0 = (t >> 5) * BM;
    int col0 = (t & 31) * BN;
    int m16base = (row0 >> 4) + wm * 4;

    // A fragment double buffer: one full kt (both ks halves) each = 32 regs.
    uint32_t afr[2][2][4][4];
    auto load_afrag = [&](int kt, int buf) {
        #pragma unroll
        for (int ks = 0; ks < 2; ks++) {
            const int k16 = kt * 2 + ks;
            #pragma unroll
            for (int mt = 0; mt < 4; mt++) {
                const size_t idx = ((size_t)(m16base + mt) * K16 + k16) * 32 + lane;
                uint4 v = __ldg(&g_A_f[idx]);      // LDG.128, coalesced
                afr[buf][ks][mt][0] = v.x;
                afr[buf][ks][mt][1] = v.y;
                afr[buf][ks][mt][2] = v.z;
                afr[buf][ks][mt][3] = v.w;
            }
        }
    };

    // Prologue: B stages 0..2 + A fragments for kt=0.
    #pragma unroll
    for (int s = 0; s < STAGES - 1; s++) {
        load_stage_B(s, s, col0);
        cp_async_commit();
    }
    load_afrag(0, 0);

    while (true) {
        float acc[4][8][4];
        #pragma unroll
        for (int i = 0; i < 4; i++)
            #pragma unroll
            for (int j = 0; j < 8; j++)
                #pragma unroll
                for (int e = 0; e < 4; e++)
                    acc[i][j][e] = 0.0f;

        for (int kt = 0; kt < KT; kt++) {
            cp_async_wait<STAGES - 2>();
            __syncthreads();

            if (kt + STAGES - 1 < KT) {
                load_stage_B(kt + STAGES - 1, (kt + STAGES - 1) & (STAGES - 1), col0);
                cp_async_commit();
            }

            const int cur = kt & 1;
            // A for kt+1: 8 coalesced LDG.128, consumed next iteration (~1k cyc).
            if (kt + 1 < KT) load_afrag(kt + 1, cur ^ 1);

            const __half* Bsb = Bs(kt & (STAGES - 1));
            uint32_t bfr[2][4][4];
            #pragma unroll
            for (int ks = 0; ks < 2; ks++)
                #pragma unroll
                for (int nt2 = 0; nt2 < 4; nt2++)
                    ldmatrix_x4_trans(bfr[ks][nt2],
                        Bsb + (ks * 16 + lrow) * LDB_S + wn * 64 + nt2 * 16 + lcol);

            #pragma unroll
            for (int ks = 0; ks < 2; ks++)
                #pragma unroll
                for (int mt = 0; mt < 4; mt++)
                    #pragma unroll
                    for (int nt = 0; nt < 8; nt++)
                        mma_16816(acc[mt][nt], afr[cur][ks][mt],
                                  &bfr[ks][nt >> 1][(nt & 1) * 2]);
        }
        cp_async_wait<0>();

        // Next tile's prologue before this epilogue.
        const int erow0 = row0, ecol0 = col0;
        int t2 = fetch_ticket();     // barriers protect smem reuse
        const bool more = (t2 < NTILES);
        if (more) {
            row0 = (t2 >> 5) * BM;
            col0 = (t2 & 31) * BN;
            m16base = (row0 >> 4) + wm * 4;
            #pragma unroll
            for (int s = 0; s < STAGES - 1; s++) {
                load_stage_B(s, s, col0);
                cp_async_commit();
            }
            load_afrag(0, 0);
        }

        // Epilogue: direct float2 stores with fused bias.
        #pragma unroll
        for (int mt = 0; mt < 4; mt++) {
            const int r = erow0 + wm * 64 + mt * 16 + (lane >> 2);
            float* o0 = out + (size_t)r * OUT_DIM;
            float* o1 = out + (size_t)(r + 8) * OUT_DIM;
            #pragma unroll
            for (int nt = 0; nt < 8; nt++) {
                const int c = ecol0 + wn * 64 + nt * 8 + 2 * (lane & 3);
                float2 bb = *reinterpret_cast<const float2*>(bias + c);
                float2 v0 = { acc[mt][nt][0] + bb.x, acc[mt][nt][1] + bb.y };
                float2 v1 = { acc[mt][nt][2] + bb.x, acc[mt][nt][3] + bb.y };
                *reinterpret_cast<float2*>(o0 + c) = v0;
                *reinterpret_cast<float2*>(o1 + c) = v1;
            }
        }

        if (!more) break;
    }
}

// ---------------------------------------------------------------------------
// Launch
// ---------------------------------------------------------------------------
extern "C" void kernel_launch(void* const* d_in, const int* in_sizes, int n_in,
                              void* d_out, int out_size) {
    const float* x    = (const float*)d_in[0];  // [2048, 4096] fp32
    const int*   idx  = (const int*)  d_in[1];  // [4096, 4096] int32
    const float* mean = (const float*)d_in[2];  // [4096] fp32
    const float* bias = (const float*)d_in[3];  // [4096] fp32
    float* out = (float*)d_out;                 // [2048, 4096] fp32

    // 1) fused prep: decode W || pack A fragments; resets ticket
    prep_kernel<<<DEC_BLOCKS + AFR_BLOCKS, 256>>>(
        (const int4*)idx, mean, x);

    // 2) persistent fp16 GEMM + bias (A from packed fragments, B via smem)
    cudaFuncSetAttribute(gemm_fp16_kernel,
                         cudaFuncAttributeMaxDynamicSharedMemorySize, SMEM_BYTES);
    gemm_fp16_kernel<<<NWORKERS, 128, SMEM_BYTES>>>(bias, out);
}

// round 12
// speedup vs baseline: 1.6939x; 1.6939x over previous
#include <cuda_runtime.h>
#include <cuda_fp16.h>
#include <cstdint>

// ---------------------------------------------------------------------------
// Problem dims
// ---------------------------------------------------------------------------
#define BATCH   2048
#define IN_DIM  4096   // K
#define OUT_DIM 4096   // N

// Scratch (static __device__ = sanctioned mechanism).
__device__ __align__(256) __half g_W_h[(size_t)IN_DIM * OUT_DIM];  // [K,N] fp16 (32MB)
__device__ __align__(256) __half g_A_h[(size_t)BATCH * IN_DIM];    // [M,K] fp16 (16MB)
// Producer/consumer state (reset by the last CTA each run).
__device__ int g_ticket;                 // GEMM tile ticket
__device__ int g_dec_ticket;             // W-decode chunk ticket
__device__ int g_a_done;                 // CTAs finished A-convert (296 = ready)
__device__ int g_chunks_done;            // W chunks finished (512 = all ready)
__device__ int g_done;                   // CTAs finished (reset trigger)
__device__ __align__(16) int g_slab_done[128];   // per-32-row-slab chunk count (4 = ready)

// ---------------------------------------------------------------------------
// Config
// ---------------------------------------------------------------------------
#define BM 128
#define BN 128
#define BK 32
#define KT (IN_DIM / BK)        // 128 (also: # W slabs)
#define NTILES ((BATCH / BM) * (OUT_DIM / BN))   // 512
#define NWORKERS 296
#define STAGES 4
#define LDA_S 40                // A smem row stride (halves): 80B
#define LDB_S 136               // B smem row stride (halves): 272B
#define A_STAGE_H (BM * LDA_S)  // 5120
#define B_STAGE_H (BK * LDB_S)  // 4352
#define STAGE_H   (A_STAGE_H + B_STAGE_H)
#define SMEM_BYTES (STAGES * STAGE_H * 2)   // 75776 B dynamic

#define NDEC 128                // CTAs that decode W; the rest start GEMM at once
#define NCHUNKS 512             // W decode chunks (8 k-rows each); 4 chunks / slab
#define CHUNK_INT4 (8 * OUT_DIM / 4)     // 8192 int4 per chunk
#define A_UNITS (BATCH * IN_DIM / 8)     // 1048576 units of 8 halves
#define A_PER_CTA ((A_UNITS + NWORKERS - 1) / NWORKERS)  // 3544

__device__ __forceinline__ void cp_async16(__half* smem_dst, const __half* gmem_src) {
    uint32_t s = (uint32_t)__cvta_generic_to_shared(smem_dst);
    asm volatile("cp.async.cg.shared.global [%0], [%1], 16;\n" :: "r"(s), "l"(gmem_src));
}
__device__ __forceinline__ void cp_async_commit() {
    asm volatile("cp.async.commit_group;\n" ::);
}
template <int N>
__device__ __forceinline__ void cp_async_wait() {
    asm volatile("cp.async.wait_group %0;\n" :: "n"(N));
}
__device__ __forceinline__ void ldmatrix_x4(uint32_t* r, const __half* p) {
    uint32_t a = (uint32_t)__cvta_generic_to_shared(p);
    asm volatile("ldmatrix.sync.aligned.m8n8.x4.shared.b16 {%0,%1,%2,%3}, [%4];"
                 : "=r"(r[0]), "=r"(r[1]), "=r"(r[2]), "=r"(r[3]) : "r"(a));
}
__device__ __forceinline__ void ldmatrix_x4_trans(uint32_t* r, const __half* p) {
    uint32_t a = (uint32_t)__cvta_generic_to_shared(p);
    asm volatile("ldmatrix.sync.aligned.m8n8.x4.trans.shared.b16 {%0,%1,%2,%3}, [%4];"
                 : "=r"(r[0]), "=r"(r[1]), "=r"(r[2]), "=r"(r[3]) : "r"(a));
}
__device__ __forceinline__ void mma_16816(float* d, const uint32_t* a, const uint32_t* b) {
    asm volatile(
        "mma.sync.aligned.m16n8k16.row.col.f32.f16.f16.f32 "
        "{%0,%1,%2,%3}, {%4,%5,%6,%7}, {%8,%9}, {%0,%1,%2,%3};"
        : "+f"(d[0]), "+f"(d[1]), "+f"(d[2]), "+f"(d[3])
        : "r"(a[0]), "r"(a[1]), "r"(a[2]), "r"(a[3]), "r"(b[0]), "r"(b[1]));
}
__device__ __forceinline__ int ld_acq(const int* p) {
    int v;
    asm volatile("ld.acquire.gpu.global.s32 %0, [%1];" : "=r"(v) : "l"(p) : "memory");
    return v;
}
__device__ __forceinline__ void spin_pause() {
    asm volatile("nanosleep.u32 64;" ::);
}

__global__ __launch_bounds__(128, 2) void fused_kernel(
    const int4*   __restrict__ idx,   // [K,N] int32 as int4
    const float*  __restrict__ mean,  // [K]
    const float4* __restrict__ x,     // [M,K] fp32 as float4
    const float*  __restrict__ bias,
    float*        __restrict__ out)
{
    extern __shared__ __half smem[];
    __shared__ int s_tile;
    __shared__ int s_chunk;
    __shared__ float s_mean[IN_DIM];   // 16KB LUT (decoders only, loaded by all)

    const int cta  = blockIdx.x;
    const int tid  = threadIdx.x;
    const int lane = tid & 31;
    const int warpId = tid >> 5;
    const int wm = warpId >> 1;   // M offset wm*64
    const int wn = warpId & 1;    // N offset wn*64
    const int lrow = lane & 15;
    const int lcol = (lane >> 4) * 8;

    // ======================= Phase A: convert x -> fp16 =====================
    {
        const int u0 = cta * A_PER_CTA;
        const int u1 = (u0 + A_PER_CTA < A_UNITS) ? u0 + A_PER_CTA : A_UNITS;
        for (int u = u0 + tid; u < u1; u += 128) {
            float4 v0 = x[2 * u];
            float4 v1 = x[2 * u + 1];
            __half2 h0 = __floats2half2_rn(v0.x, v0.y);
            __half2 h1 = __floats2half2_rn(v0.z, v0.w);
            __half2 h2 = __floats2half2_rn(v1.x, v1.y);
            __half2 h3 = __floats2half2_rn(v1.z, v1.w);
            uint4 pk;
            pk.x = *reinterpret_cast<uint32_t*>(&h0);
            pk.y = *reinterpret_cast<uint32_t*>(&h1);
            pk.z = *reinterpret_cast<uint32_t*>(&h2);
            pk.w = *reinterpret_cast<uint32_t*>(&h3);
            reinterpret_cast<uint4*>(g_A_h)[u] = pk;
        }
        __threadfence();
        __syncthreads();
        if (tid == 0) atomicAdd(&g_a_done, 1);
    }

    // ======================= Phase W: decode (CTAs < NDEC) ==================
    if (cta < NDEC) {
        #pragma unroll
        for (int i = tid; i < IN_DIM; i += 128) s_mean[i] = mean[i];
        __syncthreads();
        while (true) {
            if (tid == 0) s_chunk = atomicAdd(&g_dec_ticket, 1);
            __syncthreads();
            const int c = s_chunk;
            if (c >= NCHUNKS) break;
            const size_t base = (size_t)c * CHUNK_INT4 + tid;  // int4 units
            #pragma unroll 4
            for (int g = 0; g < CHUNK_INT4 / (128 * 4); g++) {
                int4 v[4];
                #pragma unroll
                for (int j = 0; j < 4; j++) v[j] = idx[base + (size_t)(g * 4 + j) * 128];
                #pragma unroll
                for (int j = 0; j < 4; j++) {
                    __half2 lo = __floats2half2_rn(s_mean[v[j].x], s_mean[v[j].y]);
                    __half2 hi = __floats2half2_rn(s_mean[v[j].z], s_mean[v[j].w]);
                    uint2 pk;
                    pk.x = *reinterpret_cast<uint32_t*>(&lo);
                    pk.y = *reinterpret_cast<uint32_t*>(&hi);
                    reinterpret_cast<uint2*>(g_W_h)[base + (size_t)(g * 4 + j) * 128] = pk;
                }
            }
            __threadfence();
            __syncthreads();
            if (tid == 0) {
                atomicAdd(&g_slab_done[c >> 2], 1);
                atomicAdd(&g_chunks_done, 1);
            }
        }
        __syncthreads();
    }

    // ======================= Phase GEMM (round-8 core + gates) =============
    auto As = [&](int s) { return smem + s * STAGE_H; };
    auto Bs = [&](int s) { return smem + s * STAGE_H + A_STAGE_H; };

    auto load_stage = [&](int kt, int s, int row0, int col0) {
        const __half* Ag = g_A_h + (size_t)row0 * IN_DIM + kt * BK;
        const __half* Bg = g_W_h + (size_t)(kt * BK) * OUT_DIM + col0;
        __half* as = As(s);
        __half* bs = Bs(s);
        #pragma unroll
        for (int p = 0; p < 4; p++) {
            int f = tid + p * 128;
            int r = f >> 2, c = (f & 3) * 8;
            cp_async16(&as[r * LDA_S + c], Ag + (size_t)r * IN_DIM + c);
        }
        #pragma unroll
        for (int p = 0; p < 4; p++) {
            int f = tid + p * 128;
            int r = f >> 4, c = (f & 15) * 8;
            cp_async16(&bs[r * LDB_S + c], Bg + (size_t)r * OUT_DIM + c);
        }
    };

    auto fetch_ticket = [&]() -> int {
        __syncthreads();
        if (tid == 0) s_tile = atomicAdd(&g_ticket, 1);
        __syncthreads();
        return s_tile;
    };

    // tid0-only gating state (cached; zero cost once everything is ready)
    bool a_rdy = false, w_all = false;
    int wmax = -1;
    auto ensure_a = [&]() {
        if (a_rdy) return;
        while (ld_acq(&g_a_done) < NWORKERS) spin_pause();
        a_rdy = true;
    };
    auto ensure_slab = [&](int s) {
        if (w_all || s <= wmax) return;
        if (ld_acq(&g_chunks_done) >= NCHUNKS) { w_all = true; return; }
        while (wmax < s) {
            if (ld_acq(&g_slab_done[wmax + 1]) >= 4) { wmax++; }
            else spin_pause();
        }
    };

    int t = fetch_ticket();
    if (t < NTILES) {
        int row0 = (t >> 5) * BM;
        int col0 = (t & 31) * BN;

        if (tid == 0) { ensure_a(); ensure_slab(STAGES - 2); }
        __syncthreads();
        #pragma unroll
        for (int s = 0; s < STAGES - 1; s++) {
            load_stage(s, s, row0, col0);
            cp_async_commit();
        }

        while (true) {
            float acc[4][8][4];
            #pragma unroll
            for (int i = 0; i < 4; i++)
                #pragma unroll
                for (int j = 0; j < 8; j++)
                    #pragma unroll
                    for (int e = 0; e < 4; e++)
                        acc[i][j][e] = 0.0f;

            for (int kt = 0; kt < KT; kt++) {
                cp_async_wait<STAGES - 2>();
                if (tid == 0 && kt + STAGES - 1 < KT) ensure_slab(kt + STAGES - 1);
                __syncthreads();

                if (kt + STAGES - 1 < KT) {
                    load_stage(kt + STAGES - 1, (kt + STAGES - 1) & (STAGES - 1), row0, col0);
                    cp_async_commit();
                }

                const __half* Asb = As(kt & (STAGES - 1));
                const __half* Bsb = Bs(kt & (STAGES - 1));

                uint32_t afr[2][4][4];
                uint32_t bfr[2][4][4];
                #pragma unroll
                for (int ks = 0; ks < 2; ks++) {
                    #pragma unroll
                    for (int mt = 0; mt < 4; mt++)
                        ldmatrix_x4(afr[ks][mt],
                            Asb + (wm * 64 + mt * 16 + lrow) * LDA_S + ks * 16 + lcol);
                    #pragma unroll
                    for (int nt2 = 0; nt2 < 4; nt2++)
                        ldmatrix_x4_trans(bfr[ks][nt2],
                            Bsb + (ks * 16 + lrow) * LDB_S + wn * 64 + nt2 * 16 + lcol);
                }
                #pragma unroll
                for (int ks = 0; ks < 2; ks++)
                    #pragma unroll
                    for (int mt = 0; mt < 4; mt++)
                        #pragma unroll
                        for (int nt = 0; nt < 8; nt++)
                            mma_16816(acc[mt][nt], afr[ks][mt], &bfr[ks][nt >> 1][(nt & 1) * 2]);
            }
            cp_async_wait<0>();

            // Next tile's prologue before this epilogue.
            const int erow0 = row0, ecol0 = col0;
            int t2 = fetch_ticket();
            const bool more = (t2 < NTILES);
            if (more) {
                row0 = (t2 >> 5) * BM;
                col0 = (t2 & 31) * BN;
                if (tid == 0) ensure_slab(STAGES - 2);
                __syncthreads();
                #pragma unroll
                for (int s = 0; s < STAGES - 1; s++) {
                    load_stage(s, s, row0, col0);
                    cp_async_commit();
                }
            }

            // Epilogue: direct float2 stores with fused bias.
            #pragma unroll
            for (int mt = 0; mt < 4; mt++) {
                const int r = erow0 + wm * 64 + mt * 16 + (lane >> 2);
                float* o0 = out + (size_t)r * OUT_DIM;
                float* o1 = out + (size_t)(r + 8) * OUT_DIM;
                #pragma unroll
                for (int nt = 0; nt < 8; nt++) {
                    const int c = ecol0 + wn * 64 + nt * 8 + 2 * (lane & 3);
                    float2 bb = *reinterpret_cast<const float2*>(bias + c);
                    float2 v0 = { acc[mt][nt][0] + bb.x, acc[mt][nt][1] + bb.y };
                    float2 v1 = { acc[mt][nt][2] + bb.x, acc[mt][nt][3] + bb.y };
                    *reinterpret_cast<float2*>(o0 + c) = v0;
                    *reinterpret_cast<float2*>(o1 + c) = v1;
                }
            }

            if (!more) break;
        }
    }

    // ======================= Reset protocol (last CTA out) ==================
    __syncthreads();
    if (tid == 0) {
        __threadfence();
        int d = atomicAdd(&g_done, 1);
        if (d == NWORKERS - 1) {
            // Everyone else has finished all polling & tickets; safe to reset.
            g_ticket = 0;
            g_dec_ticket = 0;
            g_a_done = 0;
            g_chunks_done = 0;
            #pragma unroll
            for (int s = 0; s < KT; s++) g_slab_done[s] = 0;
            __threadfence();
            g_done = 0;
            __threadfence();
        }
    }
}

// ---------------------------------------------------------------------------
// Launch
// ---------------------------------------------------------------------------
extern "C" void kernel_launch(void* const* d_in, const int* in_sizes, int n_in,
                              void* d_out, int out_size) {
    const float* xf   = (const float*)d_in[0];  // [2048, 4096] fp32
    const int*   idx  = (const int*)  d_in[1];  // [4096, 4096] int32
    const float* mean = (const float*)d_in[2];  // [4096] fp32
    const float* bias = (const float*)d_in[3];  // [4096] fp32
    float* out = (float*)d_out;                 // [2048, 4096] fp32

    cudaFuncSetAttribute(fused_kernel,
                         cudaFuncAttributeMaxDynamicSharedMemorySize, SMEM_BYTES);
    fused_kernel<<<NWORKERS, 128, SMEM_BYTES>>>(
        (const int4*)idx, mean, (const float4*)xf, bias, out);
}

// round 13
// speedup vs baseline: 1.7425x; 1.0287x over previous
#include <cuda_runtime.h>
#include <cuda_fp16.h>
#include <cstdint>

// ---------------------------------------------------------------------------
// Problem dims
// ---------------------------------------------------------------------------
#define BATCH   2048
#define IN_DIM  4096   // K
#define OUT_DIM 4096   // N

// Scratch (static __device__ = sanctioned mechanism).
__device__ __align__(256) __half g_W_h[(size_t)IN_DIM * OUT_DIM];  // [K,N] fp16 (32MB)
__device__ __align__(256) __half g_A_h[(size_t)BATCH * IN_DIM];    // [M,K] fp16 (16MB)
// Producer/consumer state (reset by the last CTA each run).
__device__ int g_ticket;                 // GEMM tile ticket
__device__ int g_dec_ticket;             // W-decode chunk ticket
__device__ int g_a_done;                 // CTAs finished A-convert (296 = ready)
__device__ int g_chunks_done;            // W chunks finished (512 = all ready)
__device__ int g_done;                   // CTAs finished (reset trigger)
__device__ __align__(16) int g_slab_done[128];   // per-32-row-slab chunk count (4 = ready)

// ---------------------------------------------------------------------------
// Config
// ---------------------------------------------------------------------------
#define BM 128
#define BN 128
#define BK 32
#define KT (IN_DIM / BK)        // 128 (also: # W slabs)
#define NTILES ((BATCH / BM) * (OUT_DIM / BN))   // 512
#define NWORKERS 296
#define STAGES 4
#define LDA_S 40                // A smem row stride (halves): 80B
#define LDB_S 136               // B smem row stride (halves): 272B
#define A_STAGE_H (BM * LDA_S)  // 5120
#define B_STAGE_H (BK * LDB_S)  // 4352
#define STAGE_H   (A_STAGE_H + B_STAGE_H)
#define SMEM_BYTES (STAGES * STAGE_H * 2)   // 75776 B dynamic

#define NDEC 128                // CTAs that decode W; the rest start GEMM at once
#define NCHUNKS 512             // W decode chunks (8 k-rows each); 4 chunks / slab
#define CHUNK_INT4 (8 * OUT_DIM / 4)     // 8192 int4 per chunk
#define A_UNITS (BATCH * IN_DIM / 8)     // 1048576 units of 8 halves
#define A_PER_CTA ((A_UNITS + NWORKERS - 1) / NWORKERS)  // 3544

__device__ __forceinline__ uint32_t smem_u32(const void* p) {
    uint32_t a;
    asm("{ .reg .u64 t; cvta.to.shared.u64 t, %1; cvt.u32.u64 %0, t; }" : "=r"(a) : "l"(p));
    return a;
}
__device__ __forceinline__ void cp_async16(__half* smem_dst, const __half* gmem_src) {
    uint32_t s = (uint32_t)__cvta_generic_to_shared(smem_dst);
    asm volatile("cp.async.cg.shared.global [%0], [%1], 16;\n" :: "r"(s), "l"(gmem_src));
}
__device__ __forceinline__ void mbar_init(uint32_t bar, uint32_t cnt) {
    asm volatile("mbarrier.init.shared.b64 [%0], %1;" :: "r"(bar), "r"(cnt) : "memory");
}
__device__ __forceinline__ void mbar_arrive(uint32_t bar) {
    asm volatile("mbarrier.arrive.shared.b64 _, [%0];" :: "r"(bar) : "memory");
}
// Arrive on mbar when ALL of this thread's prior cp.asyncs have completed.
__device__ __forceinline__ void cpasync_mbar_arrive(uint32_t bar) {
    asm volatile("cp.async.mbarrier.arrive.noinc.shared.b64 [%0];" :: "r"(bar) : "memory");
}
__device__ __forceinline__ void mbar_wait(uint32_t bar, uint32_t parity) {
    uint32_t done;
    asm volatile(
        "{\n\t.reg .pred p;\n\t"
        "mbarrier.try_wait.parity.acquire.cta.shared::cta.b64 p, [%1], %2;\n\t"
        "selp.b32 %0, 1, 0, p;\n\t}"
        : "=r"(done) : "r"(bar), "r"(parity) : "memory");
    if (!done) {
        asm volatile(
            "{\n\t.reg .pred P1;\n\t"
            "WL_%=:\n\t"
            "mbarrier.try_wait.parity.acquire.cta.shared::cta.b64 P1, [%0], %1, 0x989680;\n\t"
            "@P1 bra.uni WD_%=;\n\t"
            "bra.uni WL_%=;\n\t"
            "WD_%=:\n\t}"
            :: "r"(bar), "r"(parity) : "memory");
    }
}
__device__ __forceinline__ void ldmatrix_x4(uint32_t* r, const __half* p) {
    uint32_t a = (uint32_t)__cvta_generic_to_shared(p);
    asm volatile("ldmatrix.sync.aligned.m8n8.x4.shared.b16 {%0,%1,%2,%3}, [%4];"
                 : "=r"(r[0]), "=r"(r[1]), "=r"(r[2]), "=r"(r[3]) : "r"(a));
}
__device__ __forceinline__ void ldmatrix_x4_trans(uint32_t* r, const __half* p) {
    uint32_t a = (uint32_t)__cvta_generic_to_shared(p);
    asm volatile("ldmatrix.sync.aligned.m8n8.x4.trans.shared.b16 {%0,%1,%2,%3}, [%4];"
                 : "=r"(r[0]), "=r"(r[1]), "=r"(r[2]), "=r"(r[3]) : "r"(a));
}
__device__ __forceinline__ void mma_16816(float* d, const uint32_t* a, const uint32_t* b) {
    asm volatile(
        "mma.sync.aligned.m16n8k16.row.col.f32.f16.f16.f32 "
        "{%0,%1,%2,%3}, {%4,%5,%6,%7}, {%8,%9}, {%0,%1,%2,%3};"
        : "+f"(d[0]), "+f"(d[1]), "+f"(d[2]), "+f"(d[3])
        : "r"(a[0]), "r"(a[1]), "r"(a[2]), "r"(a[3]), "r"(b[0]), "r"(b[1]));
}
__device__ __forceinline__ int ld_acq(const int* p) {
    int v;
    asm volatile("ld.acquire.gpu.global.s32 %0, [%1];" : "=r"(v) : "l"(p) : "memory");
    return v;
}
__device__ __forceinline__ void spin_pause() {
    asm volatile("nanosleep.u32 64;" ::);
}

__global__ __launch_bounds__(128, 2) void fused_kernel(
    const int4*   __restrict__ idx,   // [K,N] int32 as int4
    const float*  __restrict__ mean,  // [K]
    const float4* __restrict__ x,     // [M,K] fp32 as float4
    const float*  __restrict__ bias,
    float*        __restrict__ out)
{
    extern __shared__ __half smem[];
    __shared__ int s_tile;
    __shared__ int s_chunk;
    __shared__ __align__(8) uint64_t s_mbar[2 * STAGES];   // full[0..3], empty[0..3]
    __shared__ float s_mean[IN_DIM];   // 16KB LUT

    const int cta  = blockIdx.x;
    const int tid  = threadIdx.x;
    const int lane = tid & 31;
    const int warpId = tid >> 5;
    const int wm = warpId >> 1;   // M offset wm*64
    const int wn = warpId & 1;    // N offset wn*64
    const int lrow = lane & 15;
    const int lcol = (lane >> 4) * 8;

    // ======================= Phase A: convert x -> fp16 =====================
    {
        const int u0 = cta * A_PER_CTA;
        const int u1 = (u0 + A_PER_CTA < A_UNITS) ? u0 + A_PER_CTA : A_UNITS;
        for (int u = u0 + tid; u < u1; u += 128) {
            float4 v0 = x[2 * u];
            float4 v1 = x[2 * u + 1];
            __half2 h0 = __floats2half2_rn(v0.x, v0.y);
            __half2 h1 = __floats2half2_rn(v0.z, v0.w);
            __half2 h2 = __floats2half2_rn(v1.x, v1.y);
            __half2 h3 = __floats2half2_rn(v1.z, v1.w);
            uint4 pk;
            pk.x = *reinterpret_cast<uint32_t*>(&h0);
            pk.y = *reinterpret_cast<uint32_t*>(&h1);
            pk.z = *reinterpret_cast<uint32_t*>(&h2);
            pk.w = *reinterpret_cast<uint32_t*>(&h3);
            reinterpret_cast<uint4*>(g_A_h)[u] = pk;
        }
        __threadfence();
        __syncthreads();
        if (tid == 0) atomicAdd(&g_a_done, 1);
    }

    // ======================= Phase W: decode (CTAs < NDEC) ==================
    if (cta < NDEC) {
        #pragma unroll
        for (int i = tid; i < IN_DIM; i += 128) s_mean[i] = mean[i];
        __syncthreads();
        while (true) {
            if (tid == 0) s_chunk = atomicAdd(&g_dec_ticket, 1);
            __syncthreads();
            const int c = s_chunk;
            if (c >= NCHUNKS) break;
            const size_t base = (size_t)c * CHUNK_INT4 + tid;  // int4 units
            #pragma unroll 4
            for (int g = 0; g < CHUNK_INT4 / (128 * 4); g++) {
                int4 v[4];
                #pragma unroll
                for (int j = 0; j < 4; j++) v[j] = idx[base + (size_t)(g * 4 + j) * 128];
                #pragma unroll
                for (int j = 0; j < 4; j++) {
                    __half2 lo = __floats2half2_rn(s_mean[v[j].x], s_mean[v[j].y]);
                    __half2 hi = __floats2half2_rn(s_mean[v[j].z], s_mean[v[j].w]);
                    uint2 pk;
                    pk.x = *reinterpret_cast<uint32_t*>(&lo);
                    pk.y = *reinterpret_cast<uint32_t*>(&hi);
                    reinterpret_cast<uint2*>(g_W_h)[base + (size_t)(g * 4 + j) * 128] = pk;
                }
            }
            __threadfence();
            __syncthreads();
            if (tid == 0) {
                atomicAdd(&g_slab_done[c >> 2], 1);
                atomicAdd(&g_chunks_done, 1);
            }
        }
        __syncthreads();
    }

    // ======================= GEMM: mbarrier warp-skew pipeline ==============
    const uint32_t mb = smem_u32(s_mbar);
    auto full_bar  = [&](int s) -> uint32_t { return mb + s * 8; };
    auto empty_bar = [&](int s) -> uint32_t { return mb + (STAGES + s) * 8; };

    if (tid == 0) {
        #pragma unroll
        for (int s = 0; s < STAGES; s++) {
            mbar_init(full_bar(s), 128);    // 128 cp.async.mbarrier.arrive per fill
            mbar_init(empty_bar(s), 128);   // 128 thread arrives per consume
        }
    }
    __syncthreads();   // barriers visible before any use

    auto As = [&](int s) { return smem + s * STAGE_H; };
    auto Bs = [&](int s) { return smem + s * STAGE_H + A_STAGE_H; };

    // Per-thread pipeline cursors (warp-uniform). Persist across tiles.
    int prod_stage = 0, prod_phase = 1;   // phase 1: first empty-wait passes
    int cons_stage = 0, cons_phase = 0;

    // tid0-only producer gating (W slabs / A readiness), cached.
    bool a_rdy = false, w_all = false;
    int wmax = -1;
    auto ensure_a = [&]() {
        if (a_rdy) return;
        while (ld_acq(&g_a_done) < NWORKERS) spin_pause();
        a_rdy = true;
    };
    auto ensure_slab = [&](int s) {
        if (w_all || s <= wmax) return;
        if (ld_acq(&g_chunks_done) >= NCHUNKS) { w_all = true; return; }
        while (wmax < s) {
            if (ld_acq(&g_slab_done[wmax + 1]) >= 4) { wmax++; }
            else spin_pause();
        }
    };

    // Produce one k-stage: wait empty, issue 8 cp.async, arrive full.
    auto produce = [&](int kt, int row0, int col0) {
        mbar_wait(empty_bar(prod_stage), (uint32_t)prod_phase);
        const __half* Ag = g_A_h + (size_t)row0 * IN_DIM + kt * BK;
        const __half* Bg = g_W_h + (size_t)(kt * BK) * OUT_DIM + col0;
        __half* as = As(prod_stage);
        __half* bs = Bs(prod_stage);
        #pragma unroll
        for (int p = 0; p < 4; p++) {
            int f = tid + p * 128;
            int r = f >> 2, c = (f & 3) * 8;
            cp_async16(&as[r * LDA_S + c], Ag + (size_t)r * IN_DIM + c);
        }
        #pragma unroll
        for (int p = 0; p < 4; p++) {
            int f = tid + p * 128;
            int r = f >> 4, c = (f & 15) * 8;
            cp_async16(&bs[r * LDB_S + c], Bg + (size_t)r * OUT_DIM + c);
        }
        cpasync_mbar_arrive(full_bar(prod_stage));
        if (++prod_stage == STAGES) { prod_stage = 0; prod_phase ^= 1; }
    };

    auto fetch_ticket = [&]() -> int {
        __syncthreads();
        if (tid == 0) s_tile = atomicAdd(&g_ticket, 1);
        __syncthreads();
        return s_tile;
    };

    int t = fetch_ticket();
    if (t < NTILES) {
        int row0 = (t >> 5) * BM;
        int col0 = (t & 31) * BN;

        if (tid == 0) { ensure_a(); ensure_slab(STAGES - 2); }
        __syncthreads();
        #pragma unroll
        for (int s = 0; s < STAGES - 1; s++) produce(s, row0, col0);

        while (true) {
            float acc[4][8][4];
            #pragma unroll
            for (int i = 0; i < 4; i++)
                #pragma unroll
                for (int j = 0; j < 8; j++)
                    #pragma unroll
                    for (int e = 0; e < 4; e++)
                        acc[i][j][e] = 0.0f;

            for (int kt = 0; kt < KT; kt++) {
                // Keep the pipeline deep; issue next stage's loads first.
                if (kt + STAGES - 1 < KT) {
                    if (tid == 0) ensure_slab(kt + STAGES - 1);
                    produce(kt + STAGES - 1, row0, col0);
                }

                // Consume stage kt (no block barrier — warps skew freely).
                mbar_wait(full_bar(cons_stage), (uint32_t)cons_phase);
                const __half* Asb = As(cons_stage);
                const __half* Bsb = Bs(cons_stage);

                uint32_t afr[2][4][4];
                uint32_t bfr[2][4][4];
                #pragma unroll
                for (int ks = 0; ks < 2; ks++) {
                    #pragma unroll
                    for (int mt = 0; mt < 4; mt++)
                        ldmatrix_x4(afr[ks][mt],
                            Asb + (wm * 64 + mt * 16 + lrow) * LDA_S + ks * 16 + lcol);
                    #pragma unroll
                    for (int nt2 = 0; nt2 < 4; nt2++)
                        ldmatrix_x4_trans(bfr[ks][nt2],
                            Bsb + (ks * 16 + lrow) * LDB_S + wn * 64 + nt2 * 16 + lcol);
                }
                mbar_arrive(empty_bar(cons_stage));   // fragments in regs; slot free
                if (++cons_stage == STAGES) { cons_stage = 0; cons_phase ^= 1; }

                #pragma unroll
                for (int ks = 0; ks < 2; ks++)
                    #pragma unroll
                    for (int mt = 0; mt < 4; mt++)
                        #pragma unroll
                        for (int nt = 0; nt < 8; nt++)
                            mma_16816(acc[mt][nt], afr[ks][mt], &bfr[ks][nt >> 1][(nt & 1) * 2]);
            }

            // Next tile's prologue before this epilogue.
            const int erow0 = row0, ecol0 = col0;
            int t2 = fetch_ticket();               // syncs all warps (pipeline drained)
            const bool more = (t2 < NTILES);
            if (more) {
                row0 = (t2 >> 5) * BM;
                col0 = (t2 & 31) * BN;
                #pragma unroll
                for (int s = 0; s < STAGES - 1; s++) produce(s, row0, col0);
            }

            // Epilogue: direct float2 stores with fused bias.
            #pragma unroll
            for (int mt = 0; mt < 4; mt++) {
                const int r = erow0 + wm * 64 + mt * 16 + (lane >> 2);
                float* o0 = out + (size_t)r * OUT_DIM;
                float* o1 = out + (size_t)(r + 8) * OUT_DIM;
                #pragma unroll
                for (int nt = 0; nt < 8; nt++) {
                    const int c = ecol0 + wn * 64 + nt * 8 + 2 * (lane & 3);
                    float2 bb = *reinterpret_cast<const float2*>(bias + c);
                    float2 v0 = { acc[mt][nt][0] + bb.x, acc[mt][nt][1] + bb.y };
                    float2 v1 = { acc[mt][nt][2] + bb.x, acc[mt][nt][3] + bb.y };
                    *reinterpret_cast<float2*>(o0 + c) = v0;
                    *reinterpret_cast<float2*>(o1 + c) = v1;
                }
            }

            if (!more) break;
        }
    }

    // ======================= Reset protocol (last CTA out) ==================
    __syncthreads();
    if (tid == 0) {
        __threadfence();
        int d = atomicAdd(&g_done, 1);
        if (d == NWORKERS - 1) {
            g_ticket = 0;
            g_dec_ticket = 0;
            g_a_done = 0;
            g_chunks_done = 0;
            #pragma unroll
            for (int s = 0; s < KT; s++) g_slab_done[s] = 0;
            __threadfence();
            g_done = 0;
            __threadfence();
        }
    }
}

// ---------------------------------------------------------------------------
// Launch
// ---------------------------------------------------------------------------
extern "C" void kernel_launch(void* const* d_in, const int* in_sizes, int n_in,
                              void* d_out, int out_size) {
    const float* xf   = (const float*)d_in[0];  // [2048, 4096] fp32
    const int*   idx  = (const int*)  d_in[1];  // [4096, 4096] int32
    const float* mean = (const float*)d_in[2];  // [4096] fp32
    const float* bias = (const float*)d_in[3];  // [4096] fp32
    float* out = (float*)d_out;                 // [2048, 4096] fp32

    cudaFuncSetAttribute(fused_kernel,
                         cudaFuncAttributeMaxDynamicSharedMemorySize, SMEM_BYTES);
    fused_kernel<<<NWORKERS, 128, SMEM_BYTES>>>(
        (const int4*)idx, mean, (const float4*)xf, bias, out);
}